// round 2
// baseline (speedup 1.0000x reference)
#include <cuda_runtime.h>
#include <cuda_bf16.h>
#include <cstdint>

#define NRELM 20000
#define NEDGEM 640000

// Scratch (allocation-free rule: __device__ globals)
__device__ float g_Ph[NRELM * 128];
__device__ float g_Pt[NRELM * 128];
__device__ float g_M [NRELM * 128];
__device__ float g_av[(size_t)NEDGEM * 8];   // exp(attn) per head, stored at CSR slot
__device__ int   g_etl[NEDGEM];              // tail index, stored at CSR slot
__device__ int   g_cnt[NRELM];
__device__ int   g_off[NRELM + 1];
__device__ int   g_cur[NRELM];
__device__ int   g_is64;

__device__ __forceinline__ float lrelu(float x) {
    return x >= 0.f ? x : 0.2f * x;
}

// ---- packed f32x2 helpers (FFMA2: ptxas never auto-fuses; PTX-only) ----
__device__ __forceinline__ unsigned long long pk2(float x, float y) {
    unsigned long long r;
    asm("mov.b64 %0, {%1, %2};" : "=l"(r) : "f"(x), "f"(y));
    return r;
}
__device__ __forceinline__ void fma2(unsigned long long& d, unsigned long long a,
                                     unsigned long long b) {
    asm("fma.rn.f32x2 %0, %1, %2, %3;" : "=l"(d) : "l"(a), "l"(b), "l"(d));
}
__device__ __forceinline__ void unpk2(float& x, float& y, unsigned long long v) {
    asm("mov.b64 {%0, %1}, %2;" : "=f"(x), "=f"(y) : "l"(v));
}

// Detect whether triplets are int64 (all high 32-bit words zero) or int32.
__global__ void k_detect(const int* __restrict__ t) {
    if (threadIdx.x == 0) {
        int any = 0;
        #pragma unroll 8
        for (int k = 0; k < 256; k++) any |= t[2 * k + 1];
        g_is64 = (any == 0) ? 1 : 0;
    }
}

__global__ void k_zero(int nrel) {
    int i = blockIdx.x * blockDim.x + threadIdx.x;
    if (i < nrel) g_cnt[i] = 0;
}

// Count edges per head relation
__global__ void k_count(const void* __restrict__ trip, int nedge) {
    int e = blockIdx.x * blockDim.x + threadIdx.x;
    if (e >= nedge) return;
    int h;
    if (g_is64) h = (int)((const long long*)trip)[(size_t)3 * e];
    else        h = ((const int*)trip)[(size_t)3 * e];
    atomicAdd(&g_cnt[h], 1);
}

// Exclusive scan over counts (single block, 1024 threads)
__global__ void k_scan(int nrel) {
    __shared__ int part[1024];
    const int t = threadIdx.x;
    const int chunk = (nrel + 1023) >> 10;
    const int begin = t * chunk;
    const int end = min(begin + chunk, nrel);
    int s = 0;
    for (int i = begin; i < end; i++) s += g_cnt[i];
    part[t] = s;
    __syncthreads();
    for (int off = 1; off < 1024; off <<= 1) {
        int v = (t >= off) ? part[t - off] : 0;
        __syncthreads();
        part[t] += v;
        __syncthreads();
    }
    int run = (t == 0) ? 0 : part[t - 1];
    for (int i = begin; i < end; i++) {
        g_off[i] = run;
        g_cur[i] = run;
        run += g_cnt[i];
    }
    if (t == 1023) g_off[nrel] = part[1023];
}

// Precompute Ph, Pt(+b), M(+b) with packed f32x2 FMAs.
// Block: 128 threads (one output column each), RPB relations per block.
#define RPB 8
__global__ void __launch_bounds__(128) k_pre(
        const float* __restrict__ emb,
        const float* __restrict__ wA, const float* __restrict__ bA,
        const float* __restrict__ wG, const float* __restrict__ bG,
        int nrel) {
    // smem: relation pairs packed as f32x2 per dim: sep[p][d]
    __shared__ unsigned long long sep[(RPB / 2) * 128];
    const int r0 = blockIdx.x * RPB;
    const int t = threadIdx.x;  // output dim 0..127

    #pragma unroll
    for (int p = 0; p < RPB / 2; p++) {
        int ra = r0 + 2 * p, rb = ra + 1;
        float ea = (ra < nrel) ? emb[(size_t)ra * 128 + t] : 0.f;
        float eb = (rb < nrel) ? emb[(size_t)rb * 128 + t] : 0.f;
        sep[p * 128 + t] = pk2(ea, eb);
    }
    __syncthreads();

    unsigned long long ah[RPB / 2], at[RPB / 2], am[RPB / 2];
    #pragma unroll
    for (int p = 0; p < RPB / 2; p++) { ah[p] = 0ull; at[p] = 0ull; am[p] = 0ull; }

    const float* wh = wA + (size_t)t * 256;
    const float* wt = wh + 128;
    const float* wg = wG + (size_t)t * 128;

    #pragma unroll 2
    for (int d = 0; d < 128; d += 4) {
        float4 h4 = *(const float4*)(wh + d);
        float4 t4 = *(const float4*)(wt + d);
        float4 g4 = *(const float4*)(wg + d);
        #pragma unroll
        for (int k = 0; k < 4; k++) {
            unsigned long long whb = pk2((&h4.x)[k], (&h4.x)[k]);
            unsigned long long wtb = pk2((&t4.x)[k], (&t4.x)[k]);
            unsigned long long wgb = pk2((&g4.x)[k], (&g4.x)[k]);
            #pragma unroll
            for (int p = 0; p < RPB / 2; p++) {
                unsigned long long a2 = sep[p * 128 + d + k];
                fma2(ah[p], a2, whb);
                fma2(at[p], a2, wtb);
                fma2(am[p], a2, wgb);
            }
        }
    }

    float bb = bA[t];
    float bg = bG[t];
    #pragma unroll
    for (int p = 0; p < RPB / 2; p++) {
        float x, y;
        int ra = r0 + 2 * p, rb = ra + 1;
        unpk2(x, y, ah[p]);
        if (ra < nrel) g_Ph[(size_t)ra * 128 + t] = x;
        if (rb < nrel) g_Ph[(size_t)rb * 128 + t] = y;
        unpk2(x, y, at[p]);
        if (ra < nrel) g_Pt[(size_t)ra * 128 + t] = x + bb;
        if (rb < nrel) g_Pt[(size_t)rb * 128 + t] = y + bb;
        unpk2(x, y, am[p]);
        if (ra < nrel) g_M[(size_t)ra * 128 + t] = x + bg;
        if (rb < nrel) g_M[(size_t)rb * 128 + t] = y + bg;
    }
}

// Pass A: per-edge attention logits -> exp -> CSR slot (+ tail record).
// One warp per edge; lane l covers dims 4l..4l+3 (head = l>>2).
__global__ void k_attn(const void* __restrict__ trip,
                       const float* __restrict__ attn_bin,
                       const float* __restrict__ attn_vec,
                       int nedge) {
    const int lane = threadIdx.x & 31;
    const int warp = (blockIdx.x * blockDim.x + threadIdx.x) >> 5;
    const int nw = (gridDim.x * blockDim.x) >> 5;
    const int is64 = g_is64;

    const float4 vec4 = *(const float4*)(attn_vec + 4 * lane);

    for (int e = warp; e < nedge; e += nw) {
        int h = 0, tl = 0, bn = 0;
        if (lane == 0) {
            if (is64) {
                const long long* T = (const long long*)trip;
                h  = (int)T[(size_t)3 * e];
                tl = (int)T[(size_t)3 * e + 1];
                bn = (int)T[(size_t)3 * e + 2];
            } else {
                const int* T = (const int*)trip;
                h  = T[(size_t)3 * e];
                tl = T[(size_t)3 * e + 1];
                bn = T[(size_t)3 * e + 2];
            }
        }
        h  = __shfl_sync(0xffffffffu, h, 0);
        tl = __shfl_sync(0xffffffffu, tl, 0);
        bn = __shfl_sync(0xffffffffu, bn, 0);

        float4 p = *(const float4*)(g_Ph + (size_t)h  * 128 + 4 * lane);
        float4 q = *(const float4*)(g_Pt + (size_t)tl * 128 + 4 * lane);
        float x0 = lrelu(p.x + q.x);
        float x1 = lrelu(p.y + q.y);
        float x2 = lrelu(p.z + q.z);
        float x3 = lrelu(p.w + q.w);
        float s = fmaf(x0, vec4.x, fmaf(x1, vec4.y, fmaf(x2, vec4.z, x3 * vec4.w)));
        s += __shfl_xor_sync(0xffffffffu, s, 1);
        s += __shfl_xor_sync(0xffffffffu, s, 2);
        float a = __shfl_sync(0xffffffffu, s, (lane & 7) * 4);

        int slot = 0;
        if (lane == 0) slot = atomicAdd(&g_cur[h], 1);
        slot = __shfl_sync(0xffffffffu, slot, 0);

        if (lane < 8) {
            float b = attn_bin[bn * 8 + lane];
            b = (b >= 0.f) ? b : 0.2f * b;
            g_av[(size_t)slot * 8 + lane] = __expf(a + b);
        }
        if (lane == 0) g_etl[slot] = tl;
    }
}

// Pass B: one warp per relation. out[r] = (sum v*m) / (sum v + 1e-16)
__global__ void k_aggr(float* __restrict__ out, int nrel) {
    const int lane = threadIdx.x & 31;
    const int warp = (blockIdx.x * blockDim.x + threadIdx.x) >> 5;
    const int nw = (gridDim.x * blockDim.x) >> 5;
    const int hh = lane >> 2;

    for (int r = warp; r < nrel; r += nw) {
        const int beg = g_off[r];
        const int end = g_off[r + 1];

        float4 acc = make_float4(0.f, 0.f, 0.f, 0.f);
        float vsum = 0.f;

        int tl_next = (beg < end) ? g_etl[beg] : 0;
        for (int s = beg; s < end; s++) {
            int tl = tl_next;
            if (s + 1 < end) tl_next = g_etl[s + 1];
            float v = g_av[(size_t)s * 8 + hh];
            float4 m = *(const float4*)(g_M + (size_t)tl * 128 + 4 * lane);
            acc.x = fmaf(v, m.x, acc.x);
            acc.y = fmaf(v, m.y, acc.y);
            acc.z = fmaf(v, m.z, acc.z);
            acc.w = fmaf(v, m.w, acc.w);
            vsum += v;
        }
        float inv = 1.f / (vsum + 1e-16f);
        float4 o = make_float4(acc.x * inv, acc.y * inv, acc.z * inv, acc.w * inv);
        *(float4*)(out + (size_t)r * 128 + 4 * lane) = o;
    }
}

extern "C" void kernel_launch(void* const* d_in, const int* in_sizes, int n_in,
                              void* d_out, int out_size) {
    const float* emb = (const float*)d_in[0];
    const void*  trip = d_in[1];
    const float* wA  = (const float*)d_in[2];
    const float* bA  = (const float*)d_in[3];
    const float* bin = (const float*)d_in[4];
    const float* vec = (const float*)d_in[5];
    const float* wG  = (const float*)d_in[6];
    const float* bG  = (const float*)d_in[7];
    float* out = (float*)d_out;

    int nrel  = in_sizes[0] / 128;
    int nedge = in_sizes[1] / 3;

    k_detect<<<1, 32>>>((const int*)trip);
    k_zero<<<(nrel + 255) / 256, 256>>>(nrel);
    k_count<<<(nedge + 255) / 256, 256>>>(trip, nedge);
    k_scan<<<1, 1024>>>(nrel);
    k_pre<<<(nrel + RPB - 1) / RPB, 128>>>(emb, wA, bA, wG, bG, nrel);
    k_attn<<<4096, 256>>>(trip, bin, vec, nedge);
    k_aggr<<<(nrel * 32 + 255) / 256, 256>>>(out, nrel);
}

// round 3
// speedup vs baseline: 1.2706x; 1.2706x over previous
#include <cuda_runtime.h>
#include <cuda_bf16.h>
#include <cstdint>

#define NRELM 20000
#define NEDGEM 640000

// Scratch (allocation-free rule: __device__ globals)
__device__ float g_Ph[NRELM * 128];
__device__ float g_Pt[NRELM * 128];
__device__ float g_M [NRELM * 128];
__device__ int   g_eid[NEDGEM];          // packed (tail | bin<<20) at CSR slot
__device__ int   g_cnt[NRELM];
__device__ int   g_off[NRELM + 1];
__device__ int   g_cur[NRELM];
__device__ int   g_is64;

__device__ __forceinline__ float lrelu(float x) {
    return x >= 0.f ? x : 0.2f * x;
}

// ---- packed f32x2 helpers (FFMA2: ptxas never auto-fuses; PTX-only) ----
__device__ __forceinline__ unsigned long long pk2(float x, float y) {
    unsigned long long r;
    asm("mov.b64 %0, {%1, %2};" : "=l"(r) : "f"(x), "f"(y));
    return r;
}
__device__ __forceinline__ void fma2(unsigned long long& d, unsigned long long a,
                                     unsigned long long b) {
    asm("fma.rn.f32x2 %0, %1, %2, %3;" : "=l"(d) : "l"(a), "l"(b), "l"(d));
}
__device__ __forceinline__ void unpk2(float& x, float& y, unsigned long long v) {
    asm("mov.b64 {%0, %1}, %2;" : "=f"(x), "=f"(y) : "l"(v));
}

// Zero counts + detect int64-vs-int32 triplets (high words all zero => int64).
__global__ void k_init(const int* __restrict__ t, int nrel) {
    int i = blockIdx.x * blockDim.x + threadIdx.x;
    if (i < nrel) g_cnt[i] = 0;
    if (blockIdx.x == 0 && threadIdx.x == 0) {
        int any = 0;
        #pragma unroll 8
        for (int k = 0; k < 256; k++) any |= t[2 * k + 1];
        g_is64 = (any == 0) ? 1 : 0;
    }
}

// Count edges per head relation
__global__ void k_count(const void* __restrict__ trip, int nedge) {
    int e = blockIdx.x * blockDim.x + threadIdx.x;
    if (e >= nedge) return;
    int h;
    if (g_is64) h = (int)((const long long*)trip)[(size_t)3 * e];
    else        h = ((const int*)trip)[(size_t)3 * e];
    atomicAdd(&g_cnt[h], 1);
}

// Exclusive scan over counts: single block, coalesced 1024-wide tiles,
// shfl warp scans (no uncoalesced chunk loops).
__global__ void k_scan(int nrel) {
    __shared__ int wsum[32];
    __shared__ int sbase;
    const int t = threadIdx.x, lane = t & 31, wid = t >> 5;
    if (t == 0) sbase = 0;
    __syncthreads();
    for (int base = 0; base < nrel; base += 1024) {
        int i = base + t;
        int x = (i < nrel) ? g_cnt[i] : 0;
        int v = x;
        #pragma unroll
        for (int o = 1; o < 32; o <<= 1) {
            int y = __shfl_up_sync(0xffffffffu, v, o);
            if (lane >= o) v += y;
        }
        if (lane == 31) wsum[wid] = v;
        __syncthreads();
        if (wid == 0) {
            int w = wsum[lane];
            #pragma unroll
            for (int o = 1; o < 32; o <<= 1) {
                int y = __shfl_up_sync(0xffffffffu, w, o);
                if (lane >= o) w += y;
            }
            wsum[lane] = w;
        }
        __syncthreads();
        int warpbase = (wid == 0) ? 0 : wsum[wid - 1];
        int excl = sbase + warpbase + v - x;
        if (i < nrel) { g_off[i] = excl; g_cur[i] = excl; }
        __syncthreads();
        if (t == 0) sbase += wsum[31];
        __syncthreads();
    }
    if (t == 0) g_off[nrel] = sbase;
}

// Assign CSR slots; store packed (tail | bin<<20).
__global__ void k_fill(const void* __restrict__ trip, int nedge) {
    int e = blockIdx.x * blockDim.x + threadIdx.x;
    if (e >= nedge) return;
    int h, tl, bn;
    if (g_is64) {
        const long long* T = (const long long*)trip;
        h  = (int)T[(size_t)3 * e];
        tl = (int)T[(size_t)3 * e + 1];
        bn = (int)T[(size_t)3 * e + 2];
    } else {
        const int* T = (const int*)trip;
        h  = T[(size_t)3 * e];
        tl = T[(size_t)3 * e + 1];
        bn = T[(size_t)3 * e + 2];
    }
    int slot = atomicAdd(&g_cur[h], 1);
    g_eid[slot] = tl | (bn << 20);
}

// Precompute Ph, Pt(+b), M(+b) with packed f32x2 FMAs.
#define RPB 8
__global__ void __launch_bounds__(128) k_pre(
        const float* __restrict__ emb,
        const float* __restrict__ wA, const float* __restrict__ bA,
        const float* __restrict__ wG, const float* __restrict__ bG,
        int nrel) {
    __shared__ unsigned long long sep[(RPB / 2) * 128];
    const int r0 = blockIdx.x * RPB;
    const int t = threadIdx.x;  // output dim 0..127

    #pragma unroll
    for (int p = 0; p < RPB / 2; p++) {
        int ra = r0 + 2 * p, rb = ra + 1;
        float ea = (ra < nrel) ? emb[(size_t)ra * 128 + t] : 0.f;
        float eb = (rb < nrel) ? emb[(size_t)rb * 128 + t] : 0.f;
        sep[p * 128 + t] = pk2(ea, eb);
    }
    __syncthreads();

    unsigned long long ah[RPB / 2], at[RPB / 2], am[RPB / 2];
    #pragma unroll
    for (int p = 0; p < RPB / 2; p++) { ah[p] = 0ull; at[p] = 0ull; am[p] = 0ull; }

    const float* wh = wA + (size_t)t * 256;
    const float* wt = wh + 128;
    const float* wg = wG + (size_t)t * 128;

    #pragma unroll 2
    for (int d = 0; d < 128; d += 4) {
        float4 h4 = *(const float4*)(wh + d);
        float4 t4 = *(const float4*)(wt + d);
        float4 g4 = *(const float4*)(wg + d);
        #pragma unroll
        for (int k = 0; k < 4; k++) {
            unsigned long long whb = pk2((&h4.x)[k], (&h4.x)[k]);
            unsigned long long wtb = pk2((&t4.x)[k], (&t4.x)[k]);
            unsigned long long wgb = pk2((&g4.x)[k], (&g4.x)[k]);
            #pragma unroll
            for (int p = 0; p < RPB / 2; p++) {
                unsigned long long a2 = sep[p * 128 + d + k];
                fma2(ah[p], a2, whb);
                fma2(at[p], a2, wtb);
                fma2(am[p], a2, wgb);
            }
        }
    }

    float bb = bA[t];
    float bg = bG[t];
    #pragma unroll
    for (int p = 0; p < RPB / 2; p++) {
        float x, y;
        int ra = r0 + 2 * p, rb = ra + 1;
        unpk2(x, y, ah[p]);
        if (ra < nrel) g_Ph[(size_t)ra * 128 + t] = x;
        if (rb < nrel) g_Ph[(size_t)rb * 128 + t] = y;
        unpk2(x, y, at[p]);
        if (ra < nrel) g_Pt[(size_t)ra * 128 + t] = x + bb;
        if (rb < nrel) g_Pt[(size_t)rb * 128 + t] = y + bb;
        unpk2(x, y, am[p]);
        if (ra < nrel) g_M[(size_t)ra * 128 + t] = x + bg;
        if (rb < nrel) g_M[(size_t)rb * 128 + t] = y + bg;
    }
}

// Fused attention + aggregation: one warp per relation.
// Lane l covers dims 4l..4l+3 (head = l>>2). Ph[r] lives in registers.
__global__ void __launch_bounds__(256) k_fused(
        const float* __restrict__ attn_bin,
        const float* __restrict__ attn_vec,
        float* __restrict__ out, int nrel) {
    __shared__ float sbin[80];  // lrelu(attn_bin), [bin*8 + head]
    const int t = threadIdx.x;
    if (t < 80) {
        float b = attn_bin[t];
        sbin[t] = (b >= 0.f) ? b : 0.2f * b;
    }
    __syncthreads();

    const int lane = t & 31;
    const int r = (blockIdx.x * blockDim.x + t) >> 5;
    if (r >= nrel) return;
    const int hh = lane >> 2;

    const float4 vec4 = *(const float4*)(attn_vec + 4 * lane);
    const float4 ph   = *(const float4*)(g_Ph + (size_t)r * 128 + 4 * lane);

    const int beg = g_off[r];
    const int end = g_off[r + 1];

    float4 acc = make_float4(0.f, 0.f, 0.f, 0.f);
    float vsum = 0.f;

    int pk_next = (beg < end) ? g_eid[beg] : 0;
    for (int s = beg; s < end; s++) {
        int pk = pk_next;
        if (s + 1 < end) pk_next = g_eid[s + 1];
        int tl = pk & 0xFFFFF;
        int bn = pk >> 20;

        float4 pt = *(const float4*)(g_Pt + (size_t)tl * 128 + 4 * lane);
        float4 m  = *(const float4*)(g_M  + (size_t)tl * 128 + 4 * lane);

        float x0 = lrelu(ph.x + pt.x);
        float x1 = lrelu(ph.y + pt.y);
        float x2 = lrelu(ph.z + pt.z);
        float x3 = lrelu(ph.w + pt.w);
        float sd = fmaf(x0, vec4.x, fmaf(x1, vec4.y, fmaf(x2, vec4.z, x3 * vec4.w)));
        sd += __shfl_xor_sync(0xffffffffu, sd, 1);
        sd += __shfl_xor_sync(0xffffffffu, sd, 2);

        float v = __expf(sd + sbin[bn * 8 + hh]);
        acc.x = fmaf(v, m.x, acc.x);
        acc.y = fmaf(v, m.y, acc.y);
        acc.z = fmaf(v, m.z, acc.z);
        acc.w = fmaf(v, m.w, acc.w);
        vsum += v;
    }

    float inv = 1.f / (vsum + 1e-16f);
    float4 o = make_float4(acc.x * inv, acc.y * inv, acc.z * inv, acc.w * inv);
    *(float4*)(out + (size_t)r * 128 + 4 * lane) = o;
}

extern "C" void kernel_launch(void* const* d_in, const int* in_sizes, int n_in,
                              void* d_out, int out_size) {
    const float* emb = (const float*)d_in[0];
    const void*  trip = d_in[1];
    const float* wA  = (const float*)d_in[2];
    const float* bA  = (const float*)d_in[3];
    const float* bin = (const float*)d_in[4];
    const float* vec = (const float*)d_in[5];
    const float* wG  = (const float*)d_in[6];
    const float* bG  = (const float*)d_in[7];
    float* out = (float*)d_out;

    int nrel  = in_sizes[0] / 128;
    int nedge = in_sizes[1] / 3;

    k_init<<<(nrel + 255) / 256, 256>>>((const int*)trip, nrel);
    k_count<<<(nedge + 255) / 256, 256>>>(trip, nedge);
    k_scan<<<1, 1024>>>(nrel);
    k_fill<<<(nedge + 255) / 256, 256>>>(trip, nedge);
    k_pre<<<(nrel + RPB - 1) / RPB, 128>>>(emb, wA, bA, wG, bG, nrel);
    k_fused<<<(nrel * 32 + 255) / 256, 256>>>(bin, vec, out, nrel);
}

// round 5
// speedup vs baseline: 1.4663x; 1.1540x over previous
#include <cuda_runtime.h>
#include <cuda_fp16.h>
#include <cstdint>

#define NRELM 20000
#define NEDGEM 640000

// Scratch (allocation-free rule: __device__ globals)
__device__ float g_Ph[NRELM * 128];                 // fp32, read once per relation
__device__ uint4 g_PM[NRELM * 32];                  // fp16 interleaved: per lane 4xPt | 4xM
__device__ int2  g_node[NEDGEM];                    // {next_edge, tail | bin<<20}
__device__ int   g_head[NRELM];                     // linked-list heads
__device__ int   g_is64;

__device__ __forceinline__ float lrelu(float x) {
    return x >= 0.f ? x : 0.2f * x;
}

// ---- packed f32x2 helpers (FFMA2: ptxas never auto-fuses; PTX-only) ----
__device__ __forceinline__ unsigned long long pk2(float x, float y) {
    unsigned long long r;
    asm("mov.b64 %0, {%1, %2};" : "=l"(r) : "f"(x), "f"(y));
    return r;
}
__device__ __forceinline__ void fma2(unsigned long long& d, unsigned long long a,
                                     unsigned long long b) {
    asm("fma.rn.f32x2 %0, %1, %2, %3;" : "=l"(d) : "l"(a), "l"(b), "l"(d));
}
__device__ __forceinline__ void unpk2(float& x, float& y, unsigned long long v) {
    asm("mov.b64 {%0, %1}, %2;" : "=f"(x), "=f"(y) : "l"(v));
}

// Launch 1: reset list heads + detect int64-vs-int32 triplets.
__global__ void k_init(const int* __restrict__ t, int nrel) {
    int i = blockIdx.x * blockDim.x + threadIdx.x;
    if (i < nrel) g_head[i] = -1;
    if (blockIdx.x == 0 && threadIdx.x == 0) {
        int any = 0;
        #pragma unroll 8
        for (int k = 0; k < 256; k++) any |= t[2 * k + 1];
        g_is64 = (any == 0) ? 1 : 0;
    }
}

// Launch 2: build per-head linked lists in one pass (no count/scan/fill).
__global__ void k_link(const void* __restrict__ trip, int nedge) {
    int e = blockIdx.x * blockDim.x + threadIdx.x;
    if (e >= nedge) return;
    int h, tl, bn;
    if (g_is64) {
        const long long* T = (const long long*)trip;
        h  = (int)T[(size_t)3 * e];
        tl = (int)T[(size_t)3 * e + 1];
        bn = (int)T[(size_t)3 * e + 2];
    } else {
        const int* T = (const int*)trip;
        h  = T[(size_t)3 * e];
        tl = T[(size_t)3 * e + 1];
        bn = T[(size_t)3 * e + 2];
    }
    int prev = atomicExch(&g_head[h], e);
    g_node[e] = make_int2(prev, tl | (bn << 20));
}

// Launch 3: precompute Ph (fp32) and interleaved fp16 PM table with f32x2 FMAs.
#define RPB 8
__global__ void __launch_bounds__(128) k_pre(
        const float* __restrict__ emb,
        const float* __restrict__ wA, const float* __restrict__ bA,
        const float* __restrict__ wG, const float* __restrict__ bG,
        int nrel) {
    __shared__ unsigned long long sep[(RPB / 2) * 128];
    const int r0 = blockIdx.x * RPB;
    const int t = threadIdx.x;  // output dim 0..127

    #pragma unroll
    for (int p = 0; p < RPB / 2; p++) {
        int ra = r0 + 2 * p, rb = ra + 1;
        float ea = (ra < nrel) ? emb[(size_t)ra * 128 + t] : 0.f;
        float eb = (rb < nrel) ? emb[(size_t)rb * 128 + t] : 0.f;
        sep[p * 128 + t] = pk2(ea, eb);
    }
    __syncthreads();

    unsigned long long ah[RPB / 2], at[RPB / 2], am[RPB / 2];
    #pragma unroll
    for (int p = 0; p < RPB / 2; p++) { ah[p] = 0ull; at[p] = 0ull; am[p] = 0ull; }

    const float* wh = wA + (size_t)t * 256;
    const float* wt = wh + 128;
    const float* wg = wG + (size_t)t * 128;

    #pragma unroll 2
    for (int d = 0; d < 128; d += 4) {
        float4 h4 = *(const float4*)(wh + d);
        float4 t4 = *(const float4*)(wt + d);
        float4 g4 = *(const float4*)(wg + d);
        #pragma unroll
        for (int k = 0; k < 4; k++) {
            unsigned long long whb = pk2((&h4.x)[k], (&h4.x)[k]);
            unsigned long long wtb = pk2((&t4.x)[k], (&t4.x)[k]);
            unsigned long long wgb = pk2((&g4.x)[k], (&g4.x)[k]);
            #pragma unroll
            for (int p = 0; p < RPB / 2; p++) {
                unsigned long long a2 = sep[p * 128 + d + k];
                fma2(ah[p], a2, whb);
                fma2(at[p], a2, wtb);
                fma2(am[p], a2, wgb);
            }
        }
    }

    const float bb = bA[t];
    const float bg = bG[t];
    const int g = t >> 2, j = t & 3;   // PM packing: 16B group g = [Pt 4 halves | M 4 halves]
    __half* PMH = (__half*)g_PM;
    #pragma unroll
    for (int p = 0; p < RPB / 2; p++) {
        int ra = r0 + 2 * p, rb = ra + 1;
        float hx, hy, tx, ty, mx, my;
        unpk2(hx, hy, ah[p]);
        unpk2(tx, ty, at[p]);
        unpk2(mx, my, am[p]);
        if (ra < nrel) {
            g_Ph[(size_t)ra * 128 + t] = hx;
            PMH[(size_t)ra * 256 + g * 8 + j]     = __float2half_rn(tx + bb);
            PMH[(size_t)ra * 256 + g * 8 + 4 + j] = __float2half_rn(mx + bg);
        }
        if (rb < nrel) {
            g_Ph[(size_t)rb * 128 + t] = hy;
            PMH[(size_t)rb * 256 + g * 8 + j]     = __float2half_rn(ty + bb);
            PMH[(size_t)rb * 256 + g * 8 + 4 + j] = __float2half_rn(my + bg);
        }
    }
}

__device__ __forceinline__ float2 h2f(unsigned u) {
    __half2 h = *(__half2*)&u;
    return __half22float2(h);
}

// Launch 4 (profiled slot): fused attention+softmax+aggregation.
// One warp per relation; lane l covers dims 4l..4l+3 (head = l>>2).
__global__ void __launch_bounds__(256) k_fused(
        const float* __restrict__ attn_bin,
        const float* __restrict__ attn_vec,
        float* __restrict__ out, int nrel) {
    __shared__ float sbin[80];  // lrelu(attn_bin) [bin*8 + head]
    const int t = threadIdx.x;
    if (t < 80) {
        float b = attn_bin[t];
        sbin[t] = (b >= 0.f) ? b : 0.2f * b;
    }
    __syncthreads();

    const int lane = t & 31;
    const int r = (blockIdx.x * blockDim.x + t) >> 5;
    if (r >= nrel) return;
    const int hh = lane >> 2;

    const float4 vec4 = *(const float4*)(attn_vec + 4 * lane);
    const float4 ph   = *(const float4*)(g_Ph + (size_t)r * 128 + 4 * lane);

    float4 acc = make_float4(0.f, 0.f, 0.f, 0.f);
    float vsum = 0.f;

    int e = g_head[r];
    int2 nd = make_int2(-1, 0);
    if (e >= 0) nd = g_node[e];

    while (e >= 0) {
        const int enext = nd.x;
        const int pk = nd.y;
        // prefetch next node (the only true dependency chain)
        int2 nd2 = nd;
        if (enext >= 0) nd2 = g_node[enext];

        const int tl = pk & 0xFFFFF;
        const int bn = pk >> 20;
        const uint4 pm = g_PM[(size_t)tl * 32 + lane];

        float2 p01 = h2f(pm.x), p23 = h2f(pm.y);
        float2 m01 = h2f(pm.z), m23 = h2f(pm.w);

        float x0 = lrelu(ph.x + p01.x);
        float x1 = lrelu(ph.y + p01.y);
        float x2 = lrelu(ph.z + p23.x);
        float x3 = lrelu(ph.w + p23.y);
        float sd = fmaf(x0, vec4.x, fmaf(x1, vec4.y, fmaf(x2, vec4.z, x3 * vec4.w)));
        sd += __shfl_xor_sync(0xffffffffu, sd, 1);
        sd += __shfl_xor_sync(0xffffffffu, sd, 2);

        float v = __expf(sd + sbin[bn * 8 + hh]);
        acc.x = fmaf(v, m01.x, acc.x);
        acc.y = fmaf(v, m01.y, acc.y);
        acc.z = fmaf(v, m23.x, acc.z);
        acc.w = fmaf(v, m23.y, acc.w);
        vsum += v;

        e = enext;
        nd = nd2;
    }

    float inv = 1.f / (vsum + 1e-16f);
    float4 o = make_float4(acc.x * inv, acc.y * inv, acc.z * inv, acc.w * inv);
    *(float4*)(out + (size_t)r * 128 + 4 * lane) = o;
}

extern "C" void kernel_launch(void* const* d_in, const int* in_sizes, int n_in,
                              void* d_out, int out_size) {
    const float* emb = (const float*)d_in[0];
    const void*  trip = d_in[1];
    const float* wA  = (const float*)d_in[2];
    const float* bA  = (const float*)d_in[3];
    const float* bin = (const float*)d_in[4];
    const float* vec = (const float*)d_in[5];
    const float* wG  = (const float*)d_in[6];
    const float* bG  = (const float*)d_in[7];
    float* out = (float*)d_out;

    int nrel  = in_sizes[0] / 128;
    int nedge = in_sizes[1] / 3;

    k_init<<<(nrel + 255) / 256, 256>>>((const int*)trip, nrel);
    k_link<<<(nedge + 255) / 256, 256>>>(trip, nedge);
    k_pre<<<(nrel + RPB - 1) / RPB, 128>>>(emb, wA, bA, wG, bG, nrel);
    k_fused<<<(nrel * 32 + 255) / 256, 256>>>(bin, vec, out, nrel);
}

// round 9
// speedup vs baseline: 1.4825x; 1.0111x over previous
#include <cuda_runtime.h>
#include <cuda_fp16.h>
#include <cstdint>

#define NRELM 20000
#define NEDGEM 640000

// Scratch (allocation-free rule: __device__ globals)
__device__ float g_Ph[NRELM * 128];                 // fp32, read once per relation
__device__ uint4 g_PM[NRELM * 32];                  // fp16 interleaved: per lane 4xPt | 4xM
__device__ int2  g_node[NEDGEM];                    // {next_edge, tail | bin<<20}
__device__ int   g_head[NRELM];                     // linked-list heads
__device__ int   g_is64;

__device__ __forceinline__ float lrelu(float x) {
    return x >= 0.f ? x : 0.2f * x;
}

// ---- packed f32x2 helpers (FFMA2: ptxas never auto-fuses; PTX-only) ----
__device__ __forceinline__ unsigned long long pk2(float x, float y) {
    unsigned long long r;
    asm("mov.b64 %0, {%1, %2};" : "=l"(r) : "f"(x), "f"(y));
    return r;
}
__device__ __forceinline__ void fma2(unsigned long long& d, unsigned long long a,
                                     unsigned long long b) {
    asm("fma.rn.f32x2 %0, %1, %2, %3;" : "=l"(d) : "l"(a), "l"(b), "l"(d));
}
__device__ __forceinline__ void unpk2(float& x, float& y, unsigned long long v) {
    asm("mov.b64 {%0, %1}, %2;" : "=f"(x), "=f"(y) : "l"(v));
}

// Launch 1: reset list heads + detect int64-vs-int32 triplets.
__global__ void k_init(const int* __restrict__ t, int nrel) {
    int i = blockIdx.x * blockDim.x + threadIdx.x;
    if (i < nrel) g_head[i] = -1;
    if (blockIdx.x == 0 && threadIdx.x == 0) {
        int any = 0;
        #pragma unroll 8
        for (int k = 0; k < 256; k++) any |= t[2 * k + 1];
        g_is64 = (any == 0) ? 1 : 0;
    }
}

// Launch 2: heterogeneous kernel.
//  - "pre" blocks (1 of every 3): projection tables, 16 relations/block,
//    256 threads = two 8-relation halves, packed f32x2 FMAs.
//  - "link" blocks (2 of every 3): build per-head linked lists (atomicExch).
// Interleaving mixes FMA-bound and latency-bound blocks on each SM.
__global__ void __launch_bounds__(256) k_prelink(
        const float* __restrict__ emb,
        const float* __restrict__ wA, const float* __restrict__ bA,
        const float* __restrict__ wG, const float* __restrict__ bG,
        const void* __restrict__ trip,
        int nrel, int nedge, int npre) {
    const int b = blockIdx.x;
    const bool is_pre = ((b % 3) == 0) && (b / 3 < npre);

    if (!is_pre) {
        // ---------- LINK ROLE ----------
        const int pre_before = min((b + 2) / 3, npre);
        const int linkid = b - pre_before;
        const int e = linkid * 256 + threadIdx.x;
        if (e >= nedge) return;
        int h, tl, bn;
        if (g_is64) {
            const long long* T = (const long long*)trip;
            h  = (int)T[(size_t)3 * e];
            tl = (int)T[(size_t)3 * e + 1];
            bn = (int)T[(size_t)3 * e + 2];
        } else {
            const int* T = (const int*)trip;
            h  = T[(size_t)3 * e];
            tl = T[(size_t)3 * e + 1];
            bn = T[(size_t)3 * e + 2];
        }
        int prev = atomicExch(&g_head[h], e);
        g_node[e] = make_int2(prev, tl | (bn << 20));
        return;
    }

    // ---------- PRE ROLE ----------
    __shared__ unsigned long long sep[8 * 128];  // 2 halves x 4 pairs x 128 dims
    const int preid = b / 3;
    const int tid = threadIdx.x;
    const int half = tid >> 7;          // 0/1: which 8-relation half
    const int t = tid & 127;            // output dim 0..127
    const int r0 = preid * 16 + half * 8;
    unsigned long long* sh = sep + half * 512;

    #pragma unroll
    for (int p = 0; p < 4; p++) {
        int ra = r0 + 2 * p, rb = ra + 1;
        float ea = (ra < nrel) ? emb[(size_t)ra * 128 + t] : 0.f;
        float eb = (rb < nrel) ? emb[(size_t)rb * 128 + t] : 0.f;
        sh[p * 128 + t] = pk2(ea, eb);
    }
    __syncthreads();

    unsigned long long ah[4], at[4], am[4];
    #pragma unroll
    for (int p = 0; p < 4; p++) { ah[p] = 0ull; at[p] = 0ull; am[p] = 0ull; }

    const float* wh = wA + (size_t)t * 256;
    const float* wt = wh + 128;
    const float* wg = wG + (size_t)t * 128;

    #pragma unroll 2
    for (int d = 0; d < 128; d += 4) {
        float4 h4 = *(const float4*)(wh + d);
        float4 t4 = *(const float4*)(wt + d);
        float4 g4 = *(const float4*)(wg + d);
        #pragma unroll
        for (int k = 0; k < 4; k++) {
            unsigned long long whb = pk2((&h4.x)[k], (&h4.x)[k]);
            unsigned long long wtb = pk2((&t4.x)[k], (&t4.x)[k]);
            unsigned long long wgb = pk2((&g4.x)[k], (&g4.x)[k]);
            #pragma unroll
            for (int p = 0; p < 4; p++) {
                unsigned long long a2 = sh[p * 128 + d + k];
                fma2(ah[p], a2, whb);
                fma2(at[p], a2, wtb);
                fma2(am[p], a2, wgb);
            }
        }
    }

    const float bb = bA[t];
    const float bg = bG[t];
    const int g = t >> 2, j = t & 3;   // PM packing: 16B group g = [Pt 4 halves | M 4 halves]
    __half* PMH = (__half*)g_PM;
    #pragma unroll
    for (int p = 0; p < 4; p++) {
        int ra = r0 + 2 * p, rb = ra + 1;
        float hx, hy, tx, ty, mx, my;
        unpk2(hx, hy, ah[p]);
        unpk2(tx, ty, at[p]);
        unpk2(mx, my, am[p]);
        if (ra < nrel) {
            g_Ph[(size_t)ra * 128 + t] = hx;
            PMH[(size_t)ra * 256 + g * 8 + j]     = __float2half_rn(tx + bb);
            PMH[(size_t)ra * 256 + g * 8 + 4 + j] = __float2half_rn(mx + bg);
        }
        if (rb < nrel) {
            g_Ph[(size_t)rb * 128 + t] = hy;
            PMH[(size_t)rb * 256 + g * 8 + j]     = __float2half_rn(ty + bb);
            PMH[(size_t)rb * 256 + g * 8 + 4 + j] = __float2half_rn(my + bg);
        }
    }
}

__device__ __forceinline__ float2 h2f(unsigned u) {
    __half2 h = *(__half2*)&u;
    return __half22float2(h);
}

// Launch 3: fused attention+softmax+aggregation.
// One warp per relation; lane l covers dims 4l..4l+3 (head = l>>2).
__global__ void __launch_bounds__(256) k_fused(
        const float* __restrict__ attn_bin,
        const float* __restrict__ attn_vec,
        float* __restrict__ out, int nrel) {
    __shared__ float sbin[80];  // lrelu(attn_bin) [bin*8 + head]
    const int t = threadIdx.x;
    if (t < 80) {
        float b = attn_bin[t];
        sbin[t] = (b >= 0.f) ? b : 0.2f * b;
    }
    __syncthreads();

    const int lane = t & 31;
    const int r = (blockIdx.x * blockDim.x + t) >> 5;
    if (r >= nrel) return;
    const int hh = lane >> 2;

    const float4 vec4 = *(const float4*)(attn_vec + 4 * lane);
    const float4 ph   = *(const float4*)(g_Ph + (size_t)r * 128 + 4 * lane);

    float4 acc = make_float4(0.f, 0.f, 0.f, 0.f);
    float vsum = 0.f;

    int e = g_head[r];
    int2 nd = make_int2(-1, 0);
    if (e >= 0) nd = g_node[e];

    while (e >= 0) {
        const int enext = nd.x;
        const int pk = nd.y;
        // prefetch next node (the only true dependency chain)
        int2 nd2 = nd;
        if (enext >= 0) nd2 = g_node[enext];

        const int tl = pk & 0xFFFFF;
        const int bn = pk >> 20;
        const uint4 pm = g_PM[(size_t)tl * 32 + lane];

        float2 p01 = h2f(pm.x), p23 = h2f(pm.y);
        float2 m01 = h2f(pm.z), m23 = h2f(pm.w);

        float x0 = lrelu(ph.x + p01.x);
        float x1 = lrelu(ph.y + p01.y);
        float x2 = lrelu(ph.z + p23.x);
        float x3 = lrelu(ph.w + p23.y);
        float sd = fmaf(x0, vec4.x, fmaf(x1, vec4.y, fmaf(x2, vec4.z, x3 * vec4.w)));
        sd += __shfl_xor_sync(0xffffffffu, sd, 1);
        sd += __shfl_xor_sync(0xffffffffu, sd, 2);

        float v = __expf(sd + sbin[bn * 8 + hh]);
        acc.x = fmaf(v, m01.x, acc.x);
        acc.y = fmaf(v, m01.y, acc.y);
        acc.z = fmaf(v, m23.x, acc.z);
        acc.w = fmaf(v, m23.y, acc.w);
        vsum += v;

        e = enext;
        nd = nd2;
    }

    float inv = 1.f / (vsum + 1e-16f);
    float4 o = make_float4(acc.x * inv, acc.y * inv, acc.z * inv, acc.w * inv);
    *(float4*)(out + (size_t)r * 128 + 4 * lane) = o;
}

extern "C" void kernel_launch(void* const* d_in, const int* in_sizes, int n_in,
                              void* d_out, int out_size) {
    const float* emb = (const float*)d_in[0];
    const void*  trip = d_in[1];
    const float* wA  = (const float*)d_in[2];
    const float* bA  = (const float*)d_in[3];
    const float* bin = (const float*)d_in[4];
    const float* vec = (const float*)d_in[5];
    const float* wG  = (const float*)d_in[6];
    const float* bG  = (const float*)d_in[7];
    float* out = (float*)d_out;

    int nrel  = in_sizes[0] / 128;
    int nedge = in_sizes[1] / 3;

    int npre  = (nrel + 15) / 16;
    int nlink = (nedge + 255) / 256;

    k_init<<<(nrel + 255) / 256, 256>>>((const int*)trip, nrel);
    k_prelink<<<npre + nlink, 256>>>(emb, wA, bA, wG, bG, trip, nrel, nedge, npre);
    k_fused<<<(nrel * 32 + 255) / 256, 256>>>(bin, vec, out, nrel);
}